// round 16
// baseline (speedup 1.0000x reference)
#include <cuda_runtime.h>
#include <math.h>

#define NTOK 2048      // b*t
#define CDIM 512       // input dim
#define DQ   2048      // query dim = 2*H*DH
#define NH   8
#define NKEY 256
#define DH   128
#define TK   32

// ---------------- scratch (device globals; no allocations allowed) ----------
__device__ float g_q [NTOK * DQ];           // 16 MB [t][p][h][d]
__device__ float g_w [NTOK * NH * TK];      // softmax weights
__device__ int   g_vi[NTOK * NH * TK];      // value row indices

// ---------------- packed f32x2 helpers --------------------------------------
__device__ __forceinline__ void ffma2(unsigned long long& d,
                                      unsigned long long a,
                                      unsigned long long b) {
  asm("fma.rn.f32x2 %0, %1, %2, %0;" : "+l"(d) : "l"(a), "l"(b));
}
__device__ __forceinline__ unsigned long long dup2(float v) {
  unsigned long long r;
  unsigned u = __float_as_uint(v);
  asm("mov.b64 %0, {%1, %1};" : "=l"(r) : "r"(u));
  return r;
}
__device__ __forceinline__ float2 unpack2(unsigned long long v) {
  unsigned lo, hi;
  asm("mov.b64 {%0, %1}, %2;" : "=r"(lo), "=r"(hi) : "l"(v));
  return make_float2(__uint_as_float(lo), __uint_as_float(hi));
}

// ---------- 1+2) Q = X @ Wq^T (fp32 FFMA) with fused LayerNorm --------------
__global__ __launch_bounds__(256, 2) void sgemm_ln(const float* __restrict__ X,
                                                   const float* __restrict__ W,
                                                   const float* __restrict__ gamma,
                                                   const float* __restrict__ beta) {
  __shared__ float As[16][132];
  __shared__ float Bs[16][132];
  __shared__ float red[128][17];
  const int tid = threadIdx.x;
  const int tm = tid >> 4;
  const int tn = tid & 15;
  const int m0 = blockIdx.y * 128;
  const int n0 = blockIdx.x * 128;
  const int ar = tid >> 1;
  const int ac = (tid & 1) * 8;

  float acc[8][8];
  #pragma unroll
  for (int i = 0; i < 8; i++)
    #pragma unroll
    for (int j = 0; j < 8; j++) acc[i][j] = 0.0f;

  for (int k0 = 0; k0 < CDIM; k0 += 16) {
    {
      const float* xp = X + (size_t)(m0 + ar) * CDIM + k0 + ac;
      float4 v0 = *(const float4*)xp;
      float4 v1 = *(const float4*)(xp + 4);
      As[ac + 0][ar] = v0.x; As[ac + 1][ar] = v0.y;
      As[ac + 2][ar] = v0.z; As[ac + 3][ar] = v0.w;
      As[ac + 4][ar] = v1.x; As[ac + 5][ar] = v1.y;
      As[ac + 6][ar] = v1.z; As[ac + 7][ar] = v1.w;
      const float* wp = W + (size_t)(n0 + ar) * CDIM + k0 + ac;
      float4 u0 = *(const float4*)wp;
      float4 u1 = *(const float4*)(wp + 4);
      Bs[ac + 0][ar] = u0.x; Bs[ac + 1][ar] = u0.y;
      Bs[ac + 2][ar] = u0.z; Bs[ac + 3][ar] = u0.w;
      Bs[ac + 4][ar] = u1.x; Bs[ac + 5][ar] = u1.y;
      Bs[ac + 6][ar] = u1.z; Bs[ac + 7][ar] = u1.w;
    }
    __syncthreads();
    #pragma unroll
    for (int k = 0; k < 16; k++) {
      float4 a0 = *(const float4*)&As[k][tm * 8];
      float4 a1 = *(const float4*)&As[k][tm * 8 + 4];
      float4 b0 = *(const float4*)&Bs[k][tn * 8];
      float4 b1 = *(const float4*)&Bs[k][tn * 8 + 4];
      float av[8] = {a0.x, a0.y, a0.z, a0.w, a1.x, a1.y, a1.z, a1.w};
      float bv[8] = {b0.x, b0.y, b0.z, b0.w, b1.x, b1.y, b1.z, b1.w};
      #pragma unroll
      for (int i = 0; i < 8; i++)
        #pragma unroll
        for (int j = 0; j < 8; j++) acc[i][j] = fmaf(av[i], bv[j], acc[i][j]);
    }
    __syncthreads();
  }

  float mean[8], rs[8];
  #pragma unroll
  for (int i = 0; i < 8; i++) {
    float s = 0.0f;
    #pragma unroll
    for (int j = 0; j < 8; j++) s += acc[i][j];
    red[tm * 8 + i][tn] = s;
  }
  __syncthreads();
  #pragma unroll
  for (int i = 0; i < 8; i++) {
    float s = 0.0f;
    #pragma unroll
    for (int c = 0; c < 16; c++) s += red[tm * 8 + i][c];
    mean[i] = s * (1.0f / 128.0f);
  }
  __syncthreads();
  #pragma unroll
  for (int i = 0; i < 8; i++) {
    float s = 0.0f;
    #pragma unroll
    for (int j = 0; j < 8; j++) {
      float d = acc[i][j] - mean[i];
      s += d * d;
    }
    red[tm * 8 + i][tn] = s;
  }
  __syncthreads();
  #pragma unroll
  for (int i = 0; i < 8; i++) {
    float s = 0.0f;
    #pragma unroll
    for (int c = 0; c < 16; c++) s += red[tm * 8 + i][c];
    rs[i] = rsqrtf(s * (1.0f / 128.0f) + 1e-5f);
  }

  float4 gm0 = __ldg((const float4*)(gamma + tn * 8));
  float4 gm1 = __ldg((const float4*)(gamma + tn * 8 + 4));
  float4 bt0 = __ldg((const float4*)(beta + tn * 8));
  float4 bt1 = __ldg((const float4*)(beta + tn * 8 + 4));
  float gv[8] = {gm0.x, gm0.y, gm0.z, gm0.w, gm1.x, gm1.y, gm1.z, gm1.w};
  float bv[8] = {bt0.x, bt0.y, bt0.z, bt0.w, bt1.x, bt1.y, bt1.z, bt1.w};

  #pragma unroll
  for (int i = 0; i < 8; i++) {
    float o[8];
    #pragma unroll
    for (int j = 0; j < 8; j++)
      o[j] = (acc[i][j] - mean[i]) * rs[i] * gv[j] + bv[j];
    float* op = g_q + (size_t)(m0 + tm * 8 + i) * DQ + n0 + tn * 8;
    *(float4*)op       = make_float4(o[0], o[1], o[2], o[3]);
    *(float4*)(op + 4) = make_float4(o[4], o[5], o[6], o[7]);
  }
}

// ---------------- bitonic helpers on u64 keys (desc, exact tie-break) -------
__device__ __forceinline__ unsigned long long kmax(unsigned long long a,
                                                   unsigned long long b) {
  return a > b ? a : b;
}
__device__ __forceinline__ unsigned long long kmin(unsigned long long a,
                                                   unsigned long long b) {
  return a < b ? a : b;
}
__device__ __forceinline__ unsigned long long merge_top32(
    unsigned long long a, unsigned long long b, int lane) {
  unsigned long long br = __shfl_sync(0xffffffffu, b, 31 - lane);
  unsigned long long m = kmax(a, br);
  #pragma unroll
  for (int j = 16; j > 0; j >>= 1) {
    unsigned long long o = __shfl_xor_sync(0xffffffffu, m, j);
    m = ((lane & j) == 0) ? kmax(m, o) : kmin(m, o);
  }
  return m;
}
__device__ __forceinline__ float key_val(unsigned long long k) {
  unsigned u = (unsigned)(k >> 8);
  return __uint_as_float((u & 0x80000000u) ? (u ^ 0x80000000u) : ~u);
}
__device__ __forceinline__ int key_idx(unsigned long long k) {
  return ((int)(k & 0xffull)) ^ 0xff;
}

__device__ __forceinline__ unsigned long long topk_warp(const float v[8],
                                                        int lane) {
  unsigned long long kk[8];
  #pragma unroll
  for (int rr = 0; rr < 8; rr++) {
    unsigned u = __float_as_uint(v[rr]);
    u = (u & 0x80000000u) ? ~u : (u | 0x80000000u);
    int idx = rr * 32 + lane;
    kk[rr] = ((unsigned long long)u << 8) | (unsigned)(idx ^ 0xff);
  }
  for (int kstep = 2; kstep <= 32; kstep <<= 1) {
    for (int j = kstep >> 1; j > 0; j >>= 1) {
      bool keepmax = (((lane & kstep) == 0) == ((lane & j) == 0));
      #pragma unroll
      for (int rr = 0; rr < 8; rr++) {
        unsigned long long o = __shfl_xor_sync(0xffffffffu, kk[rr], j);
        kk[rr] = keepmax ? kmax(kk[rr], o) : kmin(kk[rr], o);
      }
    }
  }
  kk[0] = merge_top32(kk[0], kk[1], lane);
  kk[2] = merge_top32(kk[2], kk[3], lane);
  kk[4] = merge_top32(kk[4], kk[5], lane);
  kk[6] = merge_top32(kk[6], kk[7], lane);
  kk[0] = merge_top32(kk[0], kk[2], lane);
  kk[4] = merge_top32(kk[4], kk[6], lane);
  return merge_top32(kk[0], kk[4], lane);
}

// ---- staircase candidate table: (i+1)*(j+1) <= 32, 119 pairs padded to 128 -
__device__ const unsigned short c_tbl[128] = {
  0,1,2,3,4,5,6,7,8,9,10,11,12,13,14,15,
  16,17,18,19,20,21,22,23,24,25,26,27,28,29,30,31,
  32,33,34,35,36,37,38,39,40,41,42,43,44,45,46,47,
  64,65,66,67,68,69,70,71,72,73,
  96,97,98,99,100,101,102,103,
  128,129,130,131,132,133,
  160,161,162,163,164,
  192,193,194,195,
  224,225,226,227,
  256,257,258,
  288,289,290,
  320,321, 352,353, 384,385, 416,417, 448,449, 480,481,
  512,544,576,608,640,672,704,736,768,800,832,864,896,928,960,992,
  0xFFFF,0xFFFF,0xFFFF,0xFFFF,0xFFFF,0xFFFF,0xFFFF,0xFFFF,0xFFFF
};

// ------- 3+4+5) fused dots+topk+combine; 32 tokens/CTA for 3 CTAs/SM --------
// Block: 32 tokens x one head. Warp w owns tokens t0+4w..+3; lane owns key
// columns rr*32+lane. p=0 and p=1 run sequentially reusing smem.
__global__ __launch_bounds__(256, 3) void dtc_kernel(const float* __restrict__ keys) {
  __shared__ float Qs[32][34];    // [k][token], padded
  __shared__ float Ks[32][257];   // [k][key],   padded
  const int h = blockIdx.y;               // 0..7
  const int t0 = blockIdx.x * 32;
  const int tid = threadIdx.x;
  const int lane = tid & 31;
  const int w = tid >> 5;

  unsigned long long res[2][4];

  #pragma unroll
  for (int p = 0; p < 2; p++) {
    const float* qbase = g_q + p * 1024 + h * 128;
    const float* kbase = keys + ((size_t)h * 512 + p) * 128;

    unsigned long long acc2[2][8];
    #pragma unroll
    for (int i = 0; i < 2; i++)
      #pragma unroll
      for (int rr = 0; rr < 8; rr++) acc2[i][rr] = 0ull;

    for (int kt = 0; kt < DH; kt += 32) {
      {
        int m = tid >> 3, c4 = (tid & 7) * 4;   // 32 tokens x 32 k = 1 f4/thread
        float4 v = *(const float4*)(qbase + (size_t)(t0 + m) * DQ + kt + c4);
        Qs[c4 + 0][m] = v.x; Qs[c4 + 1][m] = v.y;
        Qs[c4 + 2][m] = v.z; Qs[c4 + 3][m] = v.w;
      }
      #pragma unroll
      for (int i = 0; i < 8; i++) {
        int idx = tid + i * 256;
        int n = idx >> 3, c4 = (idx & 7) * 4;
        float4 v = *(const float4*)(kbase + (size_t)n * 256 + kt + c4);
        Ks[c4 + 0][n] = v.x; Ks[c4 + 1][n] = v.y;
        Ks[c4 + 2][n] = v.z; Ks[c4 + 3][n] = v.w;
      }
      __syncthreads();
      #pragma unroll 1
      for (int k = 0; k < 32; k++) {
        const unsigned long long* pq =
            (const unsigned long long*)&Qs[k][w * 4];   // 2 token-pairs
        unsigned long long q2[2] = {pq[0], pq[1]};
        unsigned long long kd[8];
        #pragma unroll
        for (int rr = 0; rr < 8; rr++) kd[rr] = dup2(Ks[k][rr * 32 + lane]);
        #pragma unroll
        for (int i = 0; i < 2; i++)
          #pragma unroll
          for (int rr = 0; rr < 8; rr++) ffma2(acc2[i][rr], q2[i], kd[rr]);
      }
      __syncthreads();
    }

    #pragma unroll 1
    for (int i2 = 0; i2 < 2; i2++) {
      float vlo[8], vhi[8];
      #pragma unroll
      for (int rr = 0; rr < 8; rr++) {
        float2 c = unpack2(acc2[0][rr]);
        vlo[rr] = c.x; vhi[rr] = c.y;
      }
      #pragma unroll
      for (int rr = 0; rr < 8; rr++) acc2[0][rr] = acc2[1][rr];

      res[p][2 * i2]     = topk_warp(vlo, lane);
      res[p][2 * i2 + 1] = topk_warp(vhi, lane);
    }
  }

  // ---- staircase combine + softmax per token (all in registers) ----
  #pragma unroll 1
  for (int i = 0; i < 4; i++) {
    int t = t0 + w * 4 + i;
    float sx = key_val(res[0][i]);
    float sy = key_val(res[1][i]);
    int  ixv = key_idx(res[0][i]);
    int  iyv = key_idx(res[1][i]);

    unsigned long long kc2[4];
    #pragma unroll
    for (int g = 0; g < 4; g++) {
      unsigned v = c_tbl[g * 32 + lane];
      int ci = (v == 0xFFFF) ? 0 : (int)(v >> 5);
      int cj = (v == 0xFFFF) ? 0 : (int)(v & 31);
      float s = __shfl_sync(0xffffffffu, sx, ci) +
                __shfl_sync(0xffffffffu, sy, cj);
      unsigned u = __float_as_uint(s);
      u = (u & 0x80000000u) ? ~u : (u | 0x80000000u);
      unsigned long long key =
          ((unsigned long long)u << 10) | (unsigned)((ci * 32 + cj) ^ 0x3ff);
      kc2[g] = (v == 0xFFFF) ? 0ull : key;
    }
    for (int kstep = 2; kstep <= 32; kstep <<= 1) {
      for (int j2 = kstep >> 1; j2 > 0; j2 >>= 1) {
        bool keepmax = (((lane & kstep) == 0) == ((lane & j2) == 0));
        #pragma unroll
        for (int g = 0; g < 4; g++) {
          unsigned long long o = __shfl_xor_sync(0xffffffffu, kc2[g], j2);
          kc2[g] = keepmax ? kmax(kc2[g], o) : kmin(kc2[g], o);
        }
      }
    }
    kc2[0] = merge_top32(kc2[0], kc2[1], lane);
    kc2[2] = merge_top32(kc2[2], kc2[3], lane);
    kc2[0] = merge_top32(kc2[0], kc2[2], lane);

    unsigned flat = ((unsigned)kc2[0] & 0x3ffu) ^ 0x3ffu;
    int ci = (int)(flat >> 5), cj = (int)(flat & 31);
    unsigned u = (unsigned)(kc2[0] >> 10);
    float selS = __uint_as_float((u & 0x80000000u) ? (u ^ 0x80000000u) : ~u);
    int ixw = __shfl_sync(0xffffffffu, ixv, ci);
    int iyw = __shfl_sync(0xffffffffu, iyv, cj);
    int selVI = ixw * NKEY + iyw;

    float mx = __shfl_sync(0xffffffffu, selS, 0);
    float e = expf(selS - mx);
    float sum = e;
    #pragma unroll
    for (int o = 16; o > 0; o >>= 1) sum += __shfl_xor_sync(0xffffffffu, sum, o);
    size_t ob = ((size_t)t * NH + h) * TK;
    g_w [ob + lane] = e / sum;
    g_vi[ob + lane] = selVI;
  }
}

// ---------------- 6) out[t] = sum_{h,k} w * values[vi]  (gather) ------------
__global__ __launch_bounds__(128) void gather_kernel(const float* __restrict__ values,
                                                     float* __restrict__ out) {
  __shared__ float sw[NH * TK];
  __shared__ int   sv[NH * TK];
  int t = blockIdx.x;
  int tid = threadIdx.x;
  size_t base = (size_t)t * (NH * TK);
  sw[tid]       = g_w [base + tid];
  sv[tid]       = g_vi[base + tid];
  sw[tid + 128] = g_w [base + tid + 128];
  sv[tid + 128] = g_vi[base + tid + 128];
  __syncthreads();

  const float4* V = (const float4*)values;
  float4 acc = make_float4(0.f, 0.f, 0.f, 0.f);
  #pragma unroll 4
  for (int r = 0; r < NH * TK; r++) {
    float wv = sw[r];
    float4 x = V[(size_t)sv[r] * 128 + tid];
    acc.x = fmaf(wv, x.x, acc.x);
    acc.y = fmaf(wv, x.y, acc.y);
    acc.z = fmaf(wv, x.z, acc.z);
    acc.w = fmaf(wv, x.w, acc.w);
  }
  ((float4*)out)[(size_t)t * 128 + tid] = acc;
}

// ---------------- launch (flat single-stream schedule) ----------------------
extern "C" void kernel_launch(void* const* d_in, const int* in_sizes, int n_in,
                              void* d_out, int out_size) {
  const float* x      = (const float*)d_in[0];  // (2,1024,512)
  const float* Wq     = (const float*)d_in[1];  // (2048,512)
  const float* keys   = (const float*)d_in[2];  // (8,256,2,128)
  const float* values = (const float*)d_in[3];  // (65536,512)
  const float* gamma  = (const float*)d_in[4];  // (128)
  const float* beta   = (const float*)d_in[5];  // (128)
  float* out = (float*)d_out;                   // (2,1024,512)

  sgemm_ln     <<<dim3(16, 16), 256>>>(x, Wq, gamma, beta);
  dtc_kernel   <<<dim3(64, 8), 256>>>(keys);
  gather_kernel<<<2048, 128>>>(values, out);
}

// round 17
// speedup vs baseline: 1.0816x; 1.0816x over previous
#include <cuda_runtime.h>
#include <math.h>

#define NTOK 2048      // b*t
#define CDIM 512       // input dim
#define DQ   2048      // query dim = 2*H*DH
#define NH   8
#define NKEY 256
#define DH   128
#define TK   32

// ---------------- scratch (device globals; no allocations allowed) ----------
__device__ float g_q [NTOK * DQ];           // 16 MB [t][p][h][d]
__device__ float g_w [NTOK * NH * TK];      // softmax weights
__device__ int   g_vi[NTOK * NH * TK];      // value row indices

// ---------------- packed f32x2 helpers --------------------------------------
__device__ __forceinline__ void ffma2(unsigned long long& d,
                                      unsigned long long a,
                                      unsigned long long b) {
  asm("fma.rn.f32x2 %0, %1, %2, %0;" : "+l"(d) : "l"(a), "l"(b));
}
__device__ __forceinline__ unsigned long long dup2(float v) {
  unsigned long long r;
  unsigned u = __float_as_uint(v);
  asm("mov.b64 %0, {%1, %1};" : "=l"(r) : "r"(u));
  return r;
}
__device__ __forceinline__ float2 unpack2(unsigned long long v) {
  unsigned lo, hi;
  asm("mov.b64 {%0, %1}, %2;" : "=r"(lo), "=r"(hi) : "l"(v));
  return make_float2(__uint_as_float(lo), __uint_as_float(hi));
}

// ---------- 1+2) Q = X @ Wq^T (fp32 FFMA) + fused LN, double-buffered -------
// One barrier per k-tile: LDG(next) -> compute(cur) -> STS(next^buf) -> bar.
__global__ __launch_bounds__(256, 2) void sgemm_ln(const float* __restrict__ X,
                                                   const float* __restrict__ W,
                                                   const float* __restrict__ gamma,
                                                   const float* __restrict__ beta) {
  __shared__ float As[2][16][132];
  __shared__ float Bs[2][16][132];
  __shared__ float red[128][17];
  const int tid = threadIdx.x;
  const int tm = tid >> 4;
  const int tn = tid & 15;
  const int m0 = blockIdx.y * 128;
  const int n0 = blockIdx.x * 128;
  const int ar = tid >> 1;
  const int ac = (tid & 1) * 8;

  float acc[8][8];
  #pragma unroll
  for (int i = 0; i < 8; i++)
    #pragma unroll
    for (int j = 0; j < 8; j++) acc[i][j] = 0.0f;

  // prologue: tile 0 into buffer 0
  {
    const float* xp = X + (size_t)(m0 + ar) * CDIM + ac;
    float4 v0 = *(const float4*)xp;
    float4 v1 = *(const float4*)(xp + 4);
    As[0][ac + 0][ar] = v0.x; As[0][ac + 1][ar] = v0.y;
    As[0][ac + 2][ar] = v0.z; As[0][ac + 3][ar] = v0.w;
    As[0][ac + 4][ar] = v1.x; As[0][ac + 5][ar] = v1.y;
    As[0][ac + 6][ar] = v1.z; As[0][ac + 7][ar] = v1.w;
    const float* wp = W + (size_t)(n0 + ar) * CDIM + ac;
    float4 u0 = *(const float4*)wp;
    float4 u1 = *(const float4*)(wp + 4);
    Bs[0][ac + 0][ar] = u0.x; Bs[0][ac + 1][ar] = u0.y;
    Bs[0][ac + 2][ar] = u0.z; Bs[0][ac + 3][ar] = u0.w;
    Bs[0][ac + 4][ar] = u1.x; Bs[0][ac + 5][ar] = u1.y;
    Bs[0][ac + 6][ar] = u1.z; Bs[0][ac + 7][ar] = u1.w;
  }
  __syncthreads();

  #pragma unroll 1
  for (int kt = 0; kt < 32; kt++) {
    const int cur = kt & 1;
    float4 v0, v1, u0, u1;
    const bool pf = (kt + 1 < 32);
    if (pf) {                                    // issue next-tile loads early
      const float* xp = X + (size_t)(m0 + ar) * CDIM + (kt + 1) * 16 + ac;
      v0 = *(const float4*)xp;
      v1 = *(const float4*)(xp + 4);
      const float* wp = W + (size_t)(n0 + ar) * CDIM + (kt + 1) * 16 + ac;
      u0 = *(const float4*)wp;
      u1 = *(const float4*)(wp + 4);
    }
    #pragma unroll
    for (int k = 0; k < 16; k++) {               // compute hides LDG latency
      float4 a0 = *(const float4*)&As[cur][k][tm * 8];
      float4 a1 = *(const float4*)&As[cur][k][tm * 8 + 4];
      float4 b0 = *(const float4*)&Bs[cur][k][tn * 8];
      float4 b1 = *(const float4*)&Bs[cur][k][tn * 8 + 4];
      float av[8] = {a0.x, a0.y, a0.z, a0.w, a1.x, a1.y, a1.z, a1.w};
      float bv[8] = {b0.x, b0.y, b0.z, b0.w, b1.x, b1.y, b1.z, b1.w};
      #pragma unroll
      for (int i = 0; i < 8; i++)
        #pragma unroll
        for (int j = 0; j < 8; j++) acc[i][j] = fmaf(av[i], bv[j], acc[i][j]);
    }
    if (pf) {                                    // store into the other buffer
      const int nb = cur ^ 1;
      As[nb][ac + 0][ar] = v0.x; As[nb][ac + 1][ar] = v0.y;
      As[nb][ac + 2][ar] = v0.z; As[nb][ac + 3][ar] = v0.w;
      As[nb][ac + 4][ar] = v1.x; As[nb][ac + 5][ar] = v1.y;
      As[nb][ac + 6][ar] = v1.z; As[nb][ac + 7][ar] = v1.w;
      Bs[nb][ac + 0][ar] = u0.x; Bs[nb][ac + 1][ar] = u0.y;
      Bs[nb][ac + 2][ar] = u0.z; Bs[nb][ac + 3][ar] = u0.w;
      Bs[nb][ac + 4][ar] = u1.x; Bs[nb][ac + 5][ar] = u1.y;
      Bs[nb][ac + 6][ar] = u1.z; Bs[nb][ac + 7][ar] = u1.w;
    }
    __syncthreads();
  }

  // ---- fused LayerNorm over the 128-col group ----
  float mean[8], rs[8];
  #pragma unroll
  for (int i = 0; i < 8; i++) {
    float s = 0.0f;
    #pragma unroll
    for (int j = 0; j < 8; j++) s += acc[i][j];
    red[tm * 8 + i][tn] = s;
  }
  __syncthreads();
  #pragma unroll
  for (int i = 0; i < 8; i++) {
    float s = 0.0f;
    #pragma unroll
    for (int c = 0; c < 16; c++) s += red[tm * 8 + i][c];
    mean[i] = s * (1.0f / 128.0f);
  }
  __syncthreads();
  #pragma unroll
  for (int i = 0; i < 8; i++) {
    float s = 0.0f;
    #pragma unroll
    for (int j = 0; j < 8; j++) {
      float d = acc[i][j] - mean[i];
      s += d * d;
    }
    red[tm * 8 + i][tn] = s;
  }
  __syncthreads();
  #pragma unroll
  for (int i = 0; i < 8; i++) {
    float s = 0.0f;
    #pragma unroll
    for (int c = 0; c < 16; c++) s += red[tm * 8 + i][c];
    rs[i] = rsqrtf(s * (1.0f / 128.0f) + 1e-5f);
  }

  float4 gm0 = __ldg((const float4*)(gamma + tn * 8));
  float4 gm1 = __ldg((const float4*)(gamma + tn * 8 + 4));
  float4 bt0 = __ldg((const float4*)(beta + tn * 8));
  float4 bt1 = __ldg((const float4*)(beta + tn * 8 + 4));
  float gv[8] = {gm0.x, gm0.y, gm0.z, gm0.w, gm1.x, gm1.y, gm1.z, gm1.w};
  float bv[8] = {bt0.x, bt0.y, bt0.z, bt0.w, bt1.x, bt1.y, bt1.z, bt1.w};

  #pragma unroll
  for (int i = 0; i < 8; i++) {
    float o[8];
    #pragma unroll
    for (int j = 0; j < 8; j++)
      o[j] = (acc[i][j] - mean[i]) * rs[i] * gv[j] + bv[j];
    float* op = g_q + (size_t)(m0 + tm * 8 + i) * DQ + n0 + tn * 8;
    *(float4*)op       = make_float4(o[0], o[1], o[2], o[3]);
    *(float4*)(op + 4) = make_float4(o[4], o[5], o[6], o[7]);
  }
}

// ---------------- bitonic helpers on u64 keys (desc, exact tie-break) -------
__device__ __forceinline__ unsigned long long kmax(unsigned long long a,
                                                   unsigned long long b) {
  return a > b ? a : b;
}
__device__ __forceinline__ unsigned long long kmin(unsigned long long a,
                                                   unsigned long long b) {
  return a < b ? a : b;
}
__device__ __forceinline__ unsigned long long merge_top32(
    unsigned long long a, unsigned long long b, int lane) {
  unsigned long long br = __shfl_sync(0xffffffffu, b, 31 - lane);
  unsigned long long m = kmax(a, br);
  #pragma unroll
  for (int j = 16; j > 0; j >>= 1) {
    unsigned long long o = __shfl_xor_sync(0xffffffffu, m, j);
    m = ((lane & j) == 0) ? kmax(m, o) : kmin(m, o);
  }
  return m;
}
__device__ __forceinline__ float key_val(unsigned long long k) {
  unsigned u = (unsigned)(k >> 8);
  return __uint_as_float((u & 0x80000000u) ? (u ^ 0x80000000u) : ~u);
}
__device__ __forceinline__ int key_idx(unsigned long long k) {
  return ((int)(k & 0xffull)) ^ 0xff;
}

__device__ __forceinline__ unsigned long long topk_warp(const float v[8],
                                                        int lane) {
  unsigned long long kk[8];
  #pragma unroll
  for (int rr = 0; rr < 8; rr++) {
    unsigned u = __float_as_uint(v[rr]);
    u = (u & 0x80000000u) ? ~u : (u | 0x80000000u);
    int idx = rr * 32 + lane;
    kk[rr] = ((unsigned long long)u << 8) | (unsigned)(idx ^ 0xff);
  }
  for (int kstep = 2; kstep <= 32; kstep <<= 1) {
    for (int j = kstep >> 1; j > 0; j >>= 1) {
      bool keepmax = (((lane & kstep) == 0) == ((lane & j) == 0));
      #pragma unroll
      for (int rr = 0; rr < 8; rr++) {
        unsigned long long o = __shfl_xor_sync(0xffffffffu, kk[rr], j);
        kk[rr] = keepmax ? kmax(kk[rr], o) : kmin(kk[rr], o);
      }
    }
  }
  kk[0] = merge_top32(kk[0], kk[1], lane);
  kk[2] = merge_top32(kk[2], kk[3], lane);
  kk[4] = merge_top32(kk[4], kk[5], lane);
  kk[6] = merge_top32(kk[6], kk[7], lane);
  kk[0] = merge_top32(kk[0], kk[2], lane);
  kk[4] = merge_top32(kk[4], kk[6], lane);
  return merge_top32(kk[0], kk[4], lane);
}

// ---- staircase candidate table: (i+1)*(j+1) <= 32, 119 pairs padded to 128 -
__device__ const unsigned short c_tbl[128] = {
  0,1,2,3,4,5,6,7,8,9,10,11,12,13,14,15,
  16,17,18,19,20,21,22,23,24,25,26,27,28,29,30,31,
  32,33,34,35,36,37,38,39,40,41,42,43,44,45,46,47,
  64,65,66,67,68,69,70,71,72,73,
  96,97,98,99,100,101,102,103,
  128,129,130,131,132,133,
  160,161,162,163,164,
  192,193,194,195,
  224,225,226,227,
  256,257,258,
  288,289,290,
  320,321, 352,353, 384,385, 416,417, 448,449, 480,481,
  512,544,576,608,640,672,704,736,768,800,832,864,896,928,960,992,
  0xFFFF,0xFFFF,0xFFFF,0xFFFF,0xFFFF,0xFFFF,0xFFFF,0xFFFF,0xFFFF
};

// ------- 3+4+5) fused: dots (both p) + top-32 + staircase combine + softmax -
// Block: 64 tokens x one head (R10-proven shape).
__global__ __launch_bounds__(256) void dtc_kernel(const float* __restrict__ keys) {
  __shared__ float Qs[32][66];
  __shared__ float Ks[32][257];
  const int h = blockIdx.y;
  const int t0 = blockIdx.x * 64;
  const int tid = threadIdx.x;
  const int lane = tid & 31;
  const int w = tid >> 5;

  unsigned long long res[2][8];

  #pragma unroll
  for (int p = 0; p < 2; p++) {
    const float* qbase = g_q + p * 1024 + h * 128;
    const float* kbase = keys + ((size_t)h * 512 + p) * 128;

    unsigned long long acc2[4][8];
    #pragma unroll
    for (int i = 0; i < 4; i++)
      #pragma unroll
      for (int rr = 0; rr < 8; rr++) acc2[i][rr] = 0ull;

    for (int kt = 0; kt < DH; kt += 32) {
      #pragma unroll
      for (int i = 0; i < 2; i++) {
        int idx = tid + i * 256;
        int m = idx >> 3, c4 = (idx & 7) * 4;
        float4 v = *(const float4*)(qbase + (size_t)(t0 + m) * DQ + kt + c4);
        Qs[c4 + 0][m] = v.x; Qs[c4 + 1][m] = v.y;
        Qs[c4 + 2][m] = v.z; Qs[c4 + 3][m] = v.w;
      }
      #pragma unroll
      for (int i = 0; i < 8; i++) {
        int idx = tid + i * 256;
        int n = idx >> 3, c4 = (idx & 7) * 4;
        float4 v = *(const float4*)(kbase + (size_t)n * 256 + kt + c4);
        Ks[c4 + 0][n] = v.x; Ks[c4 + 1][n] = v.y;
        Ks[c4 + 2][n] = v.z; Ks[c4 + 3][n] = v.w;
      }
      __syncthreads();
      #pragma unroll 1
      for (int k = 0; k < 32; k++) {
        const unsigned long long* pq =
            (const unsigned long long*)&Qs[k][w * 8];
        unsigned long long q2[4] = {pq[0], pq[1], pq[2], pq[3]};
        unsigned long long kd[8];
        #pragma unroll
        for (int rr = 0; rr < 8; rr++) kd[rr] = dup2(Ks[k][rr * 32 + lane]);
        #pragma unroll
        for (int i = 0; i < 4; i++)
          #pragma unroll
          for (int rr = 0; rr < 8; rr++) ffma2(acc2[i][rr], q2[i], kd[rr]);
      }
      __syncthreads();
    }

    #pragma unroll 1
    for (int i2 = 0; i2 < 4; i2++) {
      float vlo[8], vhi[8];
      #pragma unroll
      for (int rr = 0; rr < 8; rr++) {
        float2 c = unpack2(acc2[0][rr]);
        vlo[rr] = c.x; vhi[rr] = c.y;
      }
      #pragma unroll
      for (int s = 0; s < 3; s++)
        #pragma unroll
        for (int rr = 0; rr < 8; rr++) acc2[s][rr] = acc2[s + 1][rr];

      res[p][2 * i2]     = topk_warp(vlo, lane);
      res[p][2 * i2 + 1] = topk_warp(vhi, lane);
    }
  }

  #pragma unroll 1
  for (int i = 0; i < 8; i++) {
    int t = t0 + w * 8 + i;
    float sx = key_val(res[0][i]);
    float sy = key_val(res[1][i]);
    int  ixv = key_idx(res[0][i]);
    int  iyv = key_idx(res[1][i]);

    unsigned long long kc2[4];
    #pragma unroll
    for (int g = 0; g < 4; g++) {
      unsigned v = c_tbl[g * 32 + lane];
      int ci = (v == 0xFFFF) ? 0 : (int)(v >> 5);
      int cj = (v == 0xFFFF) ? 0 : (int)(v & 31);
      float s = __shfl_sync(0xffffffffu, sx, ci) +
                __shfl_sync(0xffffffffu, sy, cj);
      unsigned u = __float_as_uint(s);
      u = (u & 0x80000000u) ? ~u : (u | 0x80000000u);
      unsigned long long key =
          ((unsigned long long)u << 10) | (unsigned)((ci * 32 + cj) ^ 0x3ff);
      kc2[g] = (v == 0xFFFF) ? 0ull : key;
    }
    for (int kstep = 2; kstep <= 32; kstep <<= 1) {
      for (int j2 = kstep >> 1; j2 > 0; j2 >>= 1) {
        bool keepmax = (((lane & kstep) == 0) == ((lane & j2) == 0));
        #pragma unroll
        for (int g = 0; g < 4; g++) {
          unsigned long long o = __shfl_xor_sync(0xffffffffu, kc2[g], j2);
          kc2[g] = keepmax ? kmax(kc2[g], o) : kmin(kc2[g], o);
        }
      }
    }
    kc2[0] = merge_top32(kc2[0], kc2[1], lane);
    kc2[2] = merge_top32(kc2[2], kc2[3], lane);
    kc2[0] = merge_top32(kc2[0], kc2[2], lane);

    unsigned flat = ((unsigned)kc2[0] & 0x3ffu) ^ 0x3ffu;
    int ci = (int)(flat >> 5), cj = (int)(flat & 31);
    unsigned u = (unsigned)(kc2[0] >> 10);
    float selS = __uint_as_float((u & 0x80000000u) ? (u ^ 0x80000000u) : ~u);
    int ixw = __shfl_sync(0xffffffffu, ixv, ci);
    int iyw = __shfl_sync(0xffffffffu, iyv, cj);
    int selVI = ixw * NKEY + iyw;

    float mx = __shfl_sync(0xffffffffu, selS, 0);
    float e = expf(selS - mx);
    float sum = e;
    #pragma unroll
    for (int o = 16; o > 0; o >>= 1) sum += __shfl_xor_sync(0xffffffffu, sum, o);
    size_t ob = ((size_t)t * NH + h) * TK;
    g_w [ob + lane] = e / sum;
    g_vi[ob + lane] = selVI;
  }
}

// ---------------- 6) out[t] = sum_{h,k} w * values[vi]  (gather) ------------
__global__ __launch_bounds__(128) void gather_kernel(const float* __restrict__ values,
                                                     float* __restrict__ out) {
  __shared__ float sw[NH * TK];
  __shared__ int   sv[NH * TK];
  int t = blockIdx.x;
  int tid = threadIdx.x;
  size_t base = (size_t)t * (NH * TK);
  sw[tid]       = g_w [base + tid];
  sv[tid]       = g_vi[base + tid];
  sw[tid + 128] = g_w [base + tid + 128];
  sv[tid + 128] = g_vi[base + tid + 128];
  __syncthreads();

  const float4* V = (const float4*)values;
  float4 acc = make_float4(0.f, 0.f, 0.f, 0.f);
  #pragma unroll 4
  for (int r = 0; r < NH * TK; r++) {
    float wv = sw[r];
    float4 x = V[(size_t)sv[r] * 128 + tid];
    acc.x = fmaf(wv, x.x, acc.x);
    acc.y = fmaf(wv, x.y, acc.y);
    acc.z = fmaf(wv, x.z, acc.z);
    acc.w = fmaf(wv, x.w, acc.w);
  }
  ((float4*)out)[(size_t)t * 128 + tid] = acc;
}

// ---------------- launch (flat single-stream schedule) ----------------------
extern "C" void kernel_launch(void* const* d_in, const int* in_sizes, int n_in,
                              void* d_out, int out_size) {
  const float* x      = (const float*)d_in[0];  // (2,1024,512)
  const float* Wq     = (const float*)d_in[1];  // (2048,512)
  const float* keys   = (const float*)d_in[2];  // (8,256,2,128)
  const float* values = (const float*)d_in[3];  // (65536,512)
  const float* gamma  = (const float*)d_in[4];  // (128)
  const float* beta   = (const float*)d_in[5];  // (128)
  float* out = (float*)d_out;                   // (2,1024,512)

  sgemm_ln     <<<dim3(16, 16), 256>>>(x, Wq, gamma, beta);
  dtc_kernel   <<<dim3(32, 8), 256>>>(keys);
  gather_kernel<<<2048, 128>>>(values, out);
}